// round 2
// baseline (speedup 1.0000x reference)
#include <cuda_runtime.h>
#include <math.h>

#define B_SZ 512
#define NV_EN 30000
#define NV_CN 20000
#define KT 100
#define HD 512
#define DE 300
#define TAU_ 1.0f
#define EPS_SK 0.1f

// ---------------- device scratch (static, no allocations, 16B-aligned) ----------------
__device__ __align__(16) float g_h1[B_SZ * HD];
__device__ __align__(16) float g_h2[B_SZ * HD];
__device__ __align__(16) float g_mu[B_SZ * KT];
__device__ __align__(16) float g_lv[B_SZ * KT];
__device__ __align__(16) float g_G[NV_EN * KT];       // word-topic dot products (reused en/cn)
__device__ __align__(16) float g_beta[KT * NV_EN];    // aligned beta copy (GEMM operand)
__device__ __align__(16) float g_recon[B_SZ * NV_EN]; // reconstruction scratch (reused en/cn)
__device__ __align__(16) float g_theta_en[B_SZ * KT];
__device__ __align__(16) float g_theta_cn[B_SZ * KT];
__device__ __align__(16) float g_wnorm[NV_EN];
__device__ __align__(16) float g_tnorm[KT];
__device__ __align__(16) float g_topicT[DE * KT];
__device__ __align__(16) float g_tn[B_SZ * KT];       // normalized selected thetas
__device__ __align__(16) float g_tnT[KT * DE];        // normalized topic embeddings
__device__ __align__(16) float g_C[KT * KT];
__device__ __align__(16) float g_colsum[KT];
__device__ __align__(16) float g_acc[8]; // 0:rec_en 1:kl_en 2:rec_cn 3:kl_cn 4:closs 5:ccnt 6:align

// ---------------- generic fp32 GEMM: C = A[MxK] @ B[KxN] ----------------
// BM=BN=128, BK=16, 256 threads, 8x8 microtile. mode 0: store, 1: atomicAdd (split-K).
// REQUIRES: A, B 16-byte aligned; K % 4 == 0.
__global__ __launch_bounds__(256, 2)
void gemm128(const float* __restrict__ A, const float* __restrict__ B,
             float* __restrict__ C, int M, int N, int K,
             int kStepsPerZ, int mode)
{
    __shared__ __align__(16) float As[16][132];
    __shared__ __align__(16) float Bs[16][128];
    int tid = threadIdx.x;
    int row0 = blockIdx.y * 128;
    int col0 = blockIdx.x * 128;
    int kStart = blockIdx.z * kStepsPerZ * 16;
    if (kStart >= K) return;
    int kEnd = min(K, kStart + kStepsPerZ * 16);

    float acc[8][8];
#pragma unroll
    for (int i = 0; i < 8; i++)
#pragma unroll
        for (int j = 0; j < 8; j++) acc[i][j] = 0.f;

    int tx = tid & 15, ty = tid >> 4;

    for (int k0 = kStart; k0 < kEnd; k0 += 16) {
        // load A tile 128x16 (float4, transposed into As[kk][m])
#pragma unroll
        for (int s = 0; s < 2; s++) {
            int lin = tid + s * 256;
            int m = lin >> 2;
            int kk = (lin & 3) * 4;
            int row = row0 + m;
            int gk = k0 + kk;
            float4 v = make_float4(0.f, 0.f, 0.f, 0.f);
            if (row < M && gk < kEnd)
                v = *reinterpret_cast<const float4*>(&A[(size_t)row * K + gk]);
            As[kk + 0][m] = v.x; As[kk + 1][m] = v.y;
            As[kk + 2][m] = v.z; As[kk + 3][m] = v.w;
        }
        // load B tile 16x128 (float4)
#pragma unroll
        for (int s = 0; s < 2; s++) {
            int lin = tid + s * 256;
            int kk = lin >> 5;
            int n = (lin & 31) * 4;
            int gk = k0 + kk;
            int col = col0 + n;
            float4 v = make_float4(0.f, 0.f, 0.f, 0.f);
            if (gk < kEnd && col + 3 < N)
                v = *reinterpret_cast<const float4*>(&B[(size_t)gk * N + col]);
            else if (gk < kEnd) {
                // tail columns (N % 128 != 0): scalar loads
                if (col + 0 < N) v.x = B[(size_t)gk * N + col + 0];
                if (col + 1 < N) v.y = B[(size_t)gk * N + col + 1];
                if (col + 2 < N) v.z = B[(size_t)gk * N + col + 2];
                if (col + 3 < N) v.w = B[(size_t)gk * N + col + 3];
            }
            *reinterpret_cast<float4*>(&Bs[kk][n]) = v;
        }
        __syncthreads();
#pragma unroll
        for (int kk = 0; kk < 16; kk++) {
            float a[8], b[8];
            *(float4*)&a[0] = *(float4*)&As[kk][ty * 8];
            *(float4*)&a[4] = *(float4*)&As[kk][ty * 8 + 4];
            *(float4*)&b[0] = *(float4*)&Bs[kk][tx * 8];
            *(float4*)&b[4] = *(float4*)&Bs[kk][tx * 8 + 4];
#pragma unroll
            for (int i = 0; i < 8; i++)
#pragma unroll
                for (int j = 0; j < 8; j++)
                    acc[i][j] = fmaf(a[i], b[j], acc[i][j]);
        }
        __syncthreads();
    }

#pragma unroll
    for (int i = 0; i < 8; i++) {
        int row = row0 + ty * 8 + i;
        if (row >= M) continue;
#pragma unroll
        for (int j = 0; j < 8; j++) {
            int col = col0 + tx * 8 + j;
            if (col >= N) continue;
            if (mode == 0) C[(size_t)row * N + col] = acc[i][j];
            else atomicAdd(&C[(size_t)row * N + col], acc[i][j]);
        }
    }
}

// ---------------- elementwise helpers ----------------
__global__ void zero_kernel(float* p, int n) {
    for (int i = blockIdx.x * blockDim.x + threadIdx.x; i < n; i += gridDim.x * blockDim.x)
        p[i] = 0.f;
}

__global__ void bias_softplus(float* X, const float* __restrict__ bias, int M, int N) {
    int total = M * N;
    for (int idx = blockIdx.x * blockDim.x + threadIdx.x; idx < total; idx += gridDim.x * blockDim.x) {
        int j = idx % N;
        float v = X[idx] + bias[j];
        X[idx] = fmaxf(v, 0.f) + log1pf(expf(-fabsf(v)));
    }
}

// ---------------- z + softmax + KL (fused, one block per row) ----------------
// Writes theta to BOTH the aligned scratch (GEMM operand) and d_out (scalar stores).
__global__ void theta_kl_kernel(const float* __restrict__ mu_raw, const float* __restrict__ lv_raw,
                                const float* __restrict__ bmu, const float* __restrict__ blv,
                                const float* __restrict__ eps, float* __restrict__ theta_scratch,
                                float* __restrict__ theta_dout, float* kl_acc)
{
    int i = blockIdx.x;
    int k = threadIdx.x; // 128
    __shared__ float red[128];
    float zv = -1e30f, kl = 0.f;
    if (k < KT) {
        float mu = mu_raw[i * KT + k] + bmu[k];
        float lv = lv_raw[i * KT + k] + blv[k];
        zv = mu + eps[i * KT + k] * expf(0.5f * lv);
        kl = expf(lv) + mu * mu - 1.f - lv;
    }
    red[k] = zv; __syncthreads();
    for (int s = 64; s > 0; s >>= 1) { if (k < s) red[k] = fmaxf(red[k], red[k + s]); __syncthreads(); }
    float m = red[0]; __syncthreads();
    float e = (k < KT) ? expf(zv - m) : 0.f;
    red[k] = e; __syncthreads();
    for (int s = 64; s > 0; s >>= 1) { if (k < s) red[k] += red[k + s]; __syncthreads(); }
    float ssum = red[0]; __syncthreads();
    if (k < KT) {
        float t = e / ssum;
        theta_scratch[i * KT + k] = t;
        theta_dout[i * KT + k] = t;
    }
    red[k] = (k < KT) ? kl : 0.f; __syncthreads();
    for (int s = 64; s > 0; s >>= 1) { if (k < s) red[k] += red[k + s]; __syncthreads(); }
    if (k == 0) atomicAdd(kl_acc, 0.5f * red[0]);
}

// ---------------- row sum of squares (one warp per row) ----------------
__global__ void rownorm2_kernel(const float* __restrict__ X, float* __restrict__ out, int R, int D) {
    int warp = (blockIdx.x * blockDim.x + threadIdx.x) >> 5;
    int lane = threadIdx.x & 31;
    if (warp >= R) return;
    float s = 0.f;
    for (int d = lane; d < D; d += 32) { float v = X[(size_t)warp * D + d]; s = fmaf(v, v, s); }
    for (int o = 16; o; o >>= 1) s += __shfl_down_sync(0xffffffffu, s, o);
    if (lane == 0) out[warp] = s;
}

__global__ void transpose_topic(const float* __restrict__ T, float* __restrict__ Tt) {
    int idx = blockIdx.x * blockDim.x + threadIdx.x;
    if (idx < KT * DE) { int k = idx / DE, d = idx % DE; Tt[d * KT + k] = T[idx]; }
}

// ---------------- beta: exp(-dist/tau) + column sums ----------------
__global__ void beta_pass1(const float* __restrict__ G, const float* __restrict__ wnorm,
                           const float* __restrict__ tnorm, float* __restrict__ beta_scr,
                           float* __restrict__ colsum, int V)
{
    __shared__ float tn_s[KT];
    __shared__ float wsum[8];
    int v = blockIdx.x * 256 + threadIdx.x;
    if (threadIdx.x < KT) tn_s[threadIdx.x] = tnorm[threadIdx.x];
    __syncthreads();
    bool ok = v < V;
    float wn = ok ? wnorm[v] : 0.f;
    int lane = threadIdx.x & 31, wid = threadIdx.x >> 5;
    for (int k = 0; k < KT; k++) {
        float e = 0.f;
        if (ok) {
            float sq = wn + tn_s[k] - 2.f * G[(size_t)v * KT + k];
            float d = sqrtf(fmaxf(sq, 0.f));
            e = expf(-d / TAU_);
            beta_scr[(size_t)k * V + v] = e;
        }
        float s = e;
        for (int o = 16; o; o >>= 1) s += __shfl_down_sync(0xffffffffu, s, o);
        if (lane == 0) wsum[wid] = s;
        __syncthreads();
        if (threadIdx.x == 0) {
            float t = 0.f;
            for (int w = 0; w < 8; w++) t += wsum[w];
            atomicAdd(&colsum[k], t);
        }
        __syncthreads();
    }
}

// normalize; write BOTH aligned scratch (for recon GEMM) and d_out (scalar stores)
__global__ void beta_pass2(float* __restrict__ beta_scr, float* __restrict__ beta_dout,
                           const float* __restrict__ colsum, int V) {
    int total = KT * V;
    for (int idx = blockIdx.x * blockDim.x + threadIdx.x; idx < total; idx += gridDim.x * blockDim.x) {
        int k = idx / V;
        float b = beta_scr[idx] / colsum[k];
        beta_scr[idx] = b;
        beta_dout[idx] = b;
    }
}

// ---------------- fused recon loss: online logsumexp + dot, one block per row ----------------
__global__ void recon_loss_kernel(const float* __restrict__ x, const float* __restrict__ recon,
                                  int V, float* acc)
{
    int i = blockIdx.x;
    int tid = threadIdx.x; // 256
    float m = -1e30f, s = 0.f, dot = 0.f, sx = 0.f;
    for (int v = tid; v < V; v += 256) {
        float r = recon[(size_t)i * V + v];
        float xv = x[(size_t)i * V + v];
        if (r > m) { s = s * expf(m - r) + 1.f; m = r; }
        else s += expf(r - m);
        dot = fmaf(xv, r, dot);
        sx += xv;
    }
    __shared__ float sm[256], ss[256], sd[256], sxs[256];
    sm[tid] = m; ss[tid] = s; sd[tid] = dot; sxs[tid] = sx;
    __syncthreads();
    for (int o = 128; o; o >>= 1) {
        if (tid < o) {
            float m1 = sm[tid], s1 = ss[tid];
            float m2 = sm[tid + o], s2 = ss[tid + o];
            float M_ = fmaxf(m1, m2);
            sm[tid] = M_;
            ss[tid] = s1 * expf(m1 - M_) + s2 * expf(m2 - M_);
            sd[tid] += sd[tid + o];
            sxs[tid] += sxs[tid + o];
        }
        __syncthreads();
    }
    if (tid == 0) {
        float lse = sm[0] + logf(ss[0]);
        atomicAdd(acc, -sd[0] + sxs[0] * lse);
    }
}

// ---------------- contrastive ----------------
__global__ void select_norm_kernel(const float* __restrict__ theta_en,
                                   const float* __restrict__ theta_cn, float* __restrict__ tn)
{
    int i = blockIdx.x;
    int k = threadIdx.x; // 128
    __shared__ float red[128];
    const float* src = ((i & 1) == 0) ? theta_en : theta_cn;
    float v = (k < KT) ? src[i * KT + k] : 0.f;
    red[k] = v * v; __syncthreads();
    for (int s = 64; s > 0; s >>= 1) { if (k < s) red[k] += red[k + s]; __syncthreads(); }
    float nrm = fmaxf(sqrtf(red[0]), 1e-8f);
    if (k < KT) tn[i * KT + k] = v / nrm;
}

__global__ void contrast_kernel(const float* __restrict__ tn, const int* __restrict__ cid, float* acc)
{
    int i = blockIdx.x;
    int tid = threadIdx.x; // 256
    __shared__ float ti[KT];
    if (tid < KT) ti[tid] = tn[i * KT + tid];
    __syncthreads();
    int ci = cid[i];
    bool vi = ci > 0;
    float pos = 0.f, neg = 0.f, pcnt = 0.f;
    for (int j = tid; j < B_SZ; j += 256) {
        if (j == i) continue;
        float s = 0.f;
        const float* tj = &tn[j * KT];
#pragma unroll 4
        for (int k = 0; k < KT; k++) s = fmaf(ti[k], tj[k], s);
        float E = expf(s / TAU_);
        neg += E;
        int cj = cid[j];
        if (vi && cj > 0 && cj == ci) { pos += E; pcnt += 1.f; }
    }
    __shared__ float r1[256], r2[256], r3[256];
    r1[tid] = pos; r2[tid] = neg; r3[tid] = pcnt;
    __syncthreads();
    for (int o = 128; o; o >>= 1) {
        if (tid < o) { r1[tid] += r1[tid + o]; r2[tid] += r2[tid + o]; r3[tid] += r3[tid + o]; }
        __syncthreads();
    }
    if (tid == 0) {
        if (vi && r3[0] > 0.5f) {
            float per = -logf(r1[0] / (r1[0] + r2[0] + 1e-8f));
            atomicAdd(&acc[4], per);
            atomicAdd(&acc[5], 1.f);
        }
    }
}

// ---------------- alignment (Sinkhorn) ----------------
__global__ void norm_topic_kernel(const float* __restrict__ T, float* __restrict__ Tn) {
    int k = blockIdx.x; // 100
    int d = threadIdx.x; // 128
    __shared__ float red[128];
    float s = 0.f;
    for (int dd = d; dd < DE; dd += 128) { float v = T[k * DE + dd]; s = fmaf(v, v, s); }
    red[d] = s; __syncthreads();
    for (int o = 64; o > 0; o >>= 1) { if (d < o) red[d] += red[d + o]; __syncthreads(); }
    float nrm = fmaxf(sqrtf(red[0]), 1e-8f);
    for (int dd = d; dd < DE; dd += 128) Tn[k * DE + dd] = T[k * DE + dd] / nrm;
}

__global__ void cmat_kernel(const float* __restrict__ Tn, float* __restrict__ C) {
    int i = blockIdx.x; // 100
    __shared__ float ti[DE];
    for (int d = threadIdx.x; d < DE; d += 128) ti[d] = Tn[i * DE + d];
    __syncthreads();
    for (int j = threadIdx.x; j < KT; j += 128) {
        float s = 0.f;
        for (int d = 0; d < DE; d++) s = fmaf(ti[d], Tn[j * DE + d], s);
        C[i * KT + j] = 1.f - s;
    }
}

__global__ void sinkhorn_kernel(const float* __restrict__ C, float* acc) {
    __shared__ float Ks[KT * KT];
    __shared__ float u[KT], v[KT];
    __shared__ float red[256];
    int tid = threadIdx.x; // 256
    for (int idx = tid; idx < KT * KT; idx += 256) Ks[idx] = expf(-C[idx] / EPS_SK);
    if (tid < KT) { u[tid] = 1.f; v[tid] = 1.f; }
    __syncthreads();
    const float a = 1.f / KT;
    for (int it = 0; it < 50; it++) {
        if (tid < KT) {
            float d = 1e-8f;
            for (int j = 0; j < KT; j++) d = fmaf(Ks[tid * KT + j], v[j], d);
            u[tid] = a / d;
        }
        __syncthreads();
        if (tid < KT) {
            float d = 1e-8f;
            for (int i2 = 0; i2 < KT; i2++) d = fmaf(Ks[i2 * KT + tid], u[i2], d);
            v[tid] = a / d;
        }
        __syncthreads();
    }
    float s = 0.f;
    for (int idx = tid; idx < KT * KT; idx += 256) {
        int i2 = idx / KT, j = idx % KT;
        s += u[i2] * Ks[idx] * v[j] * C[idx];
    }
    red[tid] = s; __syncthreads();
    for (int o = 128; o; o >>= 1) { if (tid < o) red[tid] += red[tid + o]; __syncthreads(); }
    if (tid == 0) acc[6] = red[0];
}

__global__ void finalize_kernel(const float* __restrict__ acc, float* __restrict__ out) {
    float tm_en = acc[0] / (float)B_SZ + acc[1] / (float)B_SZ;
    float tm_cn = acc[2] / (float)B_SZ + acc[3] / (float)B_SZ;
    float contrast = acc[4] / (acc[5] + 1e-8f);
    float align = acc[6];
    out[0] = tm_en + tm_cn + contrast + align;
    out[1] = tm_en;
    out[2] = tm_cn;
    out[3] = contrast;
    out[4] = align;
}

// ---------------- host ----------------
static inline void launch_gemm(const float* A, const float* B, float* C,
                               int M, int N, int K, int gz, int mode)
{
    int ksteps = (K + 15) / 16;
    int per = (ksteps + gz - 1) / gz;
    dim3 grid((N + 127) / 128, (M + 127) / 128, gz);
    gemm128<<<grid, 256>>>(A, B, C, M, N, K, per, mode);
}

extern "C" void kernel_launch(void* const* d_in, const int* in_sizes, int n_in,
                              void* d_out, int out_size)
{
    const float* x_en   = (const float*)d_in[0];
    const float* x_cn   = (const float*)d_in[1];
    const int*   cid    = (const int*)  d_in[2];
    const float* eps_en = (const float*)d_in[3];
    const float* eps_cn = (const float*)d_in[4];
    const float* W1_en  = (const float*)d_in[5];
    const float* b1_en  = (const float*)d_in[6];
    const float* W2_en  = (const float*)d_in[7];
    const float* b2_en  = (const float*)d_in[8];
    const float* Wmu_en = (const float*)d_in[9];
    const float* bmu_en = (const float*)d_in[10];
    const float* Wlv_en = (const float*)d_in[11];
    const float* blv_en = (const float*)d_in[12];
    const float* W1_cn  = (const float*)d_in[13];
    const float* b1_cn  = (const float*)d_in[14];
    const float* W2_cn  = (const float*)d_in[15];
    const float* b2_cn  = (const float*)d_in[16];
    const float* Wmu_cn = (const float*)d_in[17];
    const float* bmu_cn = (const float*)d_in[18];
    const float* Wlv_cn = (const float*)d_in[19];
    const float* blv_cn = (const float*)d_in[20];
    const float* we_en  = (const float*)d_in[21];
    const float* we_cn  = (const float*)d_in[22];
    const float* topic  = (const float*)d_in[23];

    float* out = (float*)d_out;
    float* theta_en_out = out + 5;
    float* theta_cn_out = theta_en_out + B_SZ * KT;
    float* beta_en_out  = theta_cn_out + B_SZ * KT;
    float* beta_cn_out  = beta_en_out + KT * NV_EN;

    float *h1, *h2, *mu, *lv, *G, *beta, *recon, *th_en, *th_cn,
          *wn, *tnm, *tT, *tnb, *tnT, *Cm, *cs, *acc;
    cudaGetSymbolAddress((void**)&h1,    g_h1);
    cudaGetSymbolAddress((void**)&h2,    g_h2);
    cudaGetSymbolAddress((void**)&mu,    g_mu);
    cudaGetSymbolAddress((void**)&lv,    g_lv);
    cudaGetSymbolAddress((void**)&G,     g_G);
    cudaGetSymbolAddress((void**)&beta,  g_beta);
    cudaGetSymbolAddress((void**)&recon, g_recon);
    cudaGetSymbolAddress((void**)&th_en, g_theta_en);
    cudaGetSymbolAddress((void**)&th_cn, g_theta_cn);
    cudaGetSymbolAddress((void**)&wn,    g_wnorm);
    cudaGetSymbolAddress((void**)&tnm,   g_tnorm);
    cudaGetSymbolAddress((void**)&tT,    g_topicT);
    cudaGetSymbolAddress((void**)&tnb,   g_tn);
    cudaGetSymbolAddress((void**)&tnT,   g_tnT);
    cudaGetSymbolAddress((void**)&Cm,    g_C);
    cudaGetSymbolAddress((void**)&cs,    g_colsum);
    cudaGetSymbolAddress((void**)&acc,   g_acc);

    zero_kernel<<<1, 64>>>(acc, 8);

    // ===== EN encoder =====
    zero_kernel<<<1024, 256>>>(h1, B_SZ * HD);
    launch_gemm(x_en, W1_en, h1, B_SZ, HD, NV_EN, 20, 1);
    bias_softplus<<<1024, 256>>>(h1, b1_en, B_SZ, HD);
    zero_kernel<<<1024, 256>>>(h2, B_SZ * HD);
    launch_gemm(h1, W2_en, h2, B_SZ, HD, HD, 8, 1);
    bias_softplus<<<1024, 256>>>(h2, b2_en, B_SZ, HD);
    zero_kernel<<<256, 256>>>(mu, B_SZ * KT);
    zero_kernel<<<256, 256>>>(lv, B_SZ * KT);
    launch_gemm(h2, Wmu_en, mu, B_SZ, KT, HD, 16, 1);
    launch_gemm(h2, Wlv_en, lv, B_SZ, KT, HD, 16, 1);
    theta_kl_kernel<<<B_SZ, 128>>>(mu, lv, bmu_en, blv_en, eps_en, th_en, theta_en_out, acc + 1);

    // ===== CN encoder =====
    zero_kernel<<<1024, 256>>>(h1, B_SZ * HD);
    launch_gemm(x_cn, W1_cn, h1, B_SZ, HD, NV_CN, 20, 1);
    bias_softplus<<<1024, 256>>>(h1, b1_cn, B_SZ, HD);
    zero_kernel<<<1024, 256>>>(h2, B_SZ * HD);
    launch_gemm(h1, W2_cn, h2, B_SZ, HD, HD, 8, 1);
    bias_softplus<<<1024, 256>>>(h2, b2_cn, B_SZ, HD);
    zero_kernel<<<256, 256>>>(mu, B_SZ * KT);
    zero_kernel<<<256, 256>>>(lv, B_SZ * KT);
    launch_gemm(h2, Wmu_cn, mu, B_SZ, KT, HD, 16, 1);
    launch_gemm(h2, Wlv_cn, lv, B_SZ, KT, HD, 16, 1);
    theta_kl_kernel<<<B_SZ, 128>>>(mu, lv, bmu_cn, blv_cn, eps_cn, th_cn, theta_cn_out, acc + 3);

    // ===== beta (shared pieces) =====
    transpose_topic<<<(KT * DE + 255) / 256, 256>>>(topic, tT);
    rownorm2_kernel<<<(KT * 32 + 255) / 256, 256>>>(topic, tnm, KT, DE);

    // ===== beta EN + recon EN =====
    rownorm2_kernel<<<(NV_EN * 32 + 255) / 256, 256>>>(we_en, wn, NV_EN, DE);
    launch_gemm(we_en, tT, G, NV_EN, KT, DE, 1, 0);
    zero_kernel<<<1, 128>>>(cs, KT);
    beta_pass1<<<(NV_EN + 255) / 256, 256>>>(G, wn, tnm, beta, cs, NV_EN);
    beta_pass2<<<2048, 256>>>(beta, beta_en_out, cs, NV_EN);
    launch_gemm(th_en, beta, recon, B_SZ, NV_EN, KT, 1, 0);
    recon_loss_kernel<<<B_SZ, 256>>>(x_en, recon, NV_EN, acc + 0);

    // ===== beta CN + recon CN =====
    rownorm2_kernel<<<(NV_CN * 32 + 255) / 256, 256>>>(we_cn, wn, NV_CN, DE);
    launch_gemm(we_cn, tT, G, NV_CN, KT, DE, 1, 0);
    zero_kernel<<<1, 128>>>(cs, KT);
    beta_pass1<<<(NV_CN + 255) / 256, 256>>>(G, wn, tnm, beta, cs, NV_CN);
    beta_pass2<<<2048, 256>>>(beta, beta_cn_out, cs, NV_CN);
    launch_gemm(th_cn, beta, recon, B_SZ, NV_CN, KT, 1, 0);
    recon_loss_kernel<<<B_SZ, 256>>>(x_cn, recon, NV_CN, acc + 2);

    // ===== contrastive =====
    select_norm_kernel<<<B_SZ, 128>>>(th_en, th_cn, tnb);
    contrast_kernel<<<B_SZ, 256>>>(tnb, cid, acc);

    // ===== alignment =====
    norm_topic_kernel<<<KT, 128>>>(topic, tnT);
    cmat_kernel<<<KT, 128>>>(tnT, Cm);
    sinkhorn_kernel<<<1, 256>>>(Cm, acc);

    finalize_kernel<<<1, 1>>>(acc, out);
}